// round 1
// baseline (speedup 1.0000x reference)
#include <cuda_runtime.h>

#define C 32
#define H 128
#define W 256
#define YS 324      // y_sh row stride in floats (jj in [0,321), padded to mult of 4)
#define GO 66       // Gram band width: o in [0,65]
#define GS 67       // G_sh row stride (pad 1)

// Shared layout: y_sh[C*YS] zero-padded y row, then G_sh[W*GS] banded Gram.
__global__ __launch_bounds__(256, 2)
void cost_volume_kernel(const float* __restrict__ x, const float* __restrict__ y,
                        const float* __restrict__ disp, float* __restrict__ out,
                        int D) {
    extern __shared__ float sm[];
    float* y_sh = sm;                 // C * YS
    float* G_sh = sm + C * YS;        // W * GS

    const int bh = blockIdx.x;
    const int b = bh / H;
    const int h = bh - b * H;
    const int tid = threadIdx.x;

    const size_t HW = (size_t)H * W;
    const float* ybase = y + ((size_t)b * C * H + h) * W;   // + c*HW + col
    const float* xbase = x + ((size_t)b * C * H + h) * W;

    // ---- Phase 1: stage y row into smem with zero padding (implements the
    // out-of-range mask of the reference's zero-padded bilinear sample).
    // Logical column j = jj - 64; valid j in [0, W).
    for (int i = tid; i < C * YS; i += 256) {
        int c = i / YS;
        int jj = i - c * YS;
        float v = 0.0f;
        if (jj >= 64 && jj < 64 + W) v = ybase[(size_t)c * HW + (jj - 64)];
        y_sh[i] = v;
    }

    // Cache x columns w and w+1 in registers (x is only ever read at the
    // output's own w, reused across all 48 disparities and the whole band).
    float xa[C], xb[C];
    const int w = tid;                // blockDim.x == W == 256
    const bool has_b = (w + 1 < W);
    #pragma unroll
    for (int c = 0; c < C; c++) {
        xa[c] = xbase[(size_t)c * HW + w];
        xb[c] = has_b ? xbase[(size_t)c * HW + w + 1] : 0.0f;
    }
    __syncthreads();

    // ---- Phase 2: banded Gram  G[w][o] = sum_c x[c][w] * y[c][w - 64 + o]
    // (jj = w + o).  Anti-diagonal pairing: thread (w) computes (w, o0) and
    // (w+1, o0-1) for odd o0 — both read the SAME y_sh value, halving LDS.
    // Coverage: (w, odd o) from own first entry; (w, even o) from thread w-1's
    // second entry; (0, even o) handled by the cleanup loop below.
    for (int o0 = 1; o0 <= 65; o0 += 2) {
        const float* yp = y_sh + (w + o0);
        float a0 = 0.f, a1 = 0.f, b0 = 0.f, b1 = 0.f;
        #pragma unroll
        for (int c = 0; c < C; c += 2) {
            float yv0 = yp[c * YS];
            float yv1 = yp[(c + 1) * YS];
            a0 = fmaf(xa[c],     yv0, a0);
            b0 = fmaf(xb[c],     yv0, b0);
            a1 = fmaf(xa[c + 1], yv1, a1);
            b1 = fmaf(xb[c + 1], yv1, b1);
        }
        G_sh[w * GS + o0] = a0 + a1;
        if (has_b) G_sh[(w + 1) * GS + (o0 - 1)] = b0 + b1;
    }
    // Cleanup: entries (w=0, even o), 33 of them.
    if (tid < 33) {
        int o = 2 * tid;
        float a = 0.f;
        #pragma unroll
        for (int c = 0; c < C; c++)
            a = fmaf(xbase[(size_t)c * HW], y_sh[c * YS + o], a);
        G_sh[o] = a;
    }
    __syncthreads();

    // ---- Phase 3: gather + lerp.  cost = ((1-fx)*G[w][o] + fx*G[w][o+1]) / C
    // with o = floor(w - disp) - w + 64.  Zero-padded y already encodes the
    // boundary masks inside G.
    const float* dbase = disp + ((size_t)b * D * H + h) * W;
    float* obase = out + ((size_t)b * D * H + h) * W;
    const int total = D * W;
    for (int i = tid; i < total; i += 256) {
        int d = i >> 8;               // W == 256
        int ww = i & (W - 1);
        float dv = dbase[(size_t)d * HW + ww];
        float px = (float)ww - dv;
        float x0f = floorf(px);
        float fx = px - x0f;
        int o = (int)x0f - ww + 64;
        float g0 = 0.f, g1 = 0.f;
        if (o >= 0 && o < GO) g0 = G_sh[ww * GS + o];
        int o1 = o + 1;
        if (o1 >= 0 && o1 < GO) g1 = G_sh[ww * GS + o1];
        obase[(size_t)d * HW + ww] = (g0 + (g1 - g0) * fx) * (1.0f / C);
    }
}

extern "C" void kernel_launch(void* const* d_in, const int* in_sizes, int n_in,
                              void* d_out, int out_size) {
    const float* x = (const float*)d_in[0];
    const float* y = (const float*)d_in[1];
    const float* disp = (const float*)d_in[2];
    int B = in_sizes[0] / (C * H * W);
    int D = in_sizes[2] / (B * H * W);
    int smem = (C * YS + W * GS) * (int)sizeof(float);
    cudaFuncSetAttribute(cost_volume_kernel,
                         cudaFuncAttributeMaxDynamicSharedMemorySize, smem);
    cost_volume_kernel<<<B * H, 256, smem>>>(x, y, disp, (float*)d_out, D);
}

// round 2
// speedup vs baseline: 1.3754x; 1.3754x over previous
#include <cuda_runtime.h>

#define C 32
#define H 128
#define W 256
#define YS 325      // y_sh row stride; 16*YS % 32 == 16 -> halves on disjoint banks
#define GO 66       // Gram band width: o in [0,65]
#define GS 67       // G_sh row stride (pad 1)
#define NT 512

// Shared layout: y_sh[C*YS] zero-padded y row, then G_sh[W*GS] banded Gram.
__global__ __launch_bounds__(NT, 2)
void cost_volume_kernel(const float* __restrict__ x, const float* __restrict__ y,
                        const float* __restrict__ disp, float* __restrict__ out,
                        int D) {
    extern __shared__ float sm[];
    float* y_sh = sm;                 // C * YS
    float* G_sh = sm + C * YS;        // W * GS

    const int bh = blockIdx.x;
    const int b = bh / H;
    const int h = bh - b * H;
    const int tid = threadIdx.x;

    const size_t HW = (size_t)H * W;
    const float* ybase = y + ((size_t)b * C * H + h) * W;   // + c*HW + col
    const float* xbase = x + ((size_t)b * C * H + h) * W;

    // ---- Phase 1: stage y row into smem with zero padding (implements the
    // zero-padding boundary mask of the reference bilinear sample).
    for (int i = tid; i < C * YS; i += NT) {
        int c = i / YS;
        int jj = i - c * YS;
        float v = 0.0f;
        if (jj >= 64 && jj < 64 + W) v = ybase[(size_t)c * HW + (jj - 64)];
        y_sh[i] = v;
    }

    // Warp layout: each warp covers 16 w-columns; lane halves split channels.
    const int lane = tid & 31;
    const int wp = tid >> 5;            // 0..15
    const int half = lane >> 4;         // 0: c in [0,16), 1: c in [16,32)
    const int wl = lane & 15;
    const int w = wp * 16 + wl;         // 0..255
    const int cbase = half * 16;
    const bool has_b = (w + 1 < W);

    float xa[16], xb[16];
    #pragma unroll
    for (int k = 0; k < 16; k++) {
        xa[k] = xbase[(size_t)(cbase + k) * HW + w];
        xb[k] = has_b ? xbase[(size_t)(cbase + k) * HW + w + 1] : 0.0f;
    }
    __syncthreads();

    // ---- Phase 2: banded Gram  G[w][o] = sum_c x[c][w] * y_sh[c][w + o]
    // Anti-diagonal pairing: (w, o0) and (w+1, o0-1) share y_sh[c][w+o0].
    // Channel halves reduced via shfl.bfly(16); half 0 stores.
    const float* ybl = y_sh + cbase * YS + w;
    for (int o0 = 1; o0 <= 65; o0 += 2) {
        const float* yp = ybl + o0;
        float a0 = 0.f, a1 = 0.f, b0 = 0.f, b1 = 0.f;
        #pragma unroll
        for (int k = 0; k < 16; k += 2) {
            float yv0 = yp[k * YS];
            float yv1 = yp[(k + 1) * YS];
            a0 = fmaf(xa[k],     yv0, a0);
            b0 = fmaf(xb[k],     yv0, b0);
            a1 = fmaf(xa[k + 1], yv1, a1);
            b1 = fmaf(xb[k + 1], yv1, b1);
        }
        float av = a0 + a1, bv = b0 + b1;
        av += __shfl_xor_sync(0xFFFFFFFFu, av, 16);
        bv += __shfl_xor_sync(0xFFFFFFFFu, bv, 16);
        if (half == 0) {
            G_sh[w * GS + o0] = av;
            if (has_b) G_sh[(w + 1) * GS + (o0 - 1)] = bv;
        }
    }
    // Cleanup: entries (w=0, even o), 33 of them.
    if (tid < 33) {
        int o = 2 * tid;
        float a = 0.f;
        #pragma unroll
        for (int c = 0; c < C; c++)
            a = fmaf(xbase[(size_t)c * HW], y_sh[c * YS + o], a);
        G_sh[o] = a;
    }
    __syncthreads();

    // ---- Phase 3: gather + lerp.  cost = ((1-fx)*G[w][o] + fx*G[w][o+1]) / C
    const float* dbase = disp + ((size_t)b * D * H + h) * W;
    float* obase = out + ((size_t)b * D * H + h) * W;
    const int total = D * W;
    for (int i = tid; i < total; i += NT) {
        int d = i >> 8;               // W == 256
        int ww = i & (W - 1);
        float dv = dbase[(size_t)d * HW + ww];
        float px = (float)ww - dv;
        float x0f = floorf(px);
        float fx = px - x0f;
        int o = (int)x0f - ww + 64;
        float g0 = (o >= 0 && o < GO) ? G_sh[ww * GS + o] : 0.f;
        int o1 = o + 1;
        float g1 = (o1 >= 0 && o1 < GO) ? G_sh[ww * GS + o1] : 0.f;
        obase[(size_t)d * HW + ww] = (g0 + (g1 - g0) * fx) * (1.0f / C);
    }
}

extern "C" void kernel_launch(void* const* d_in, const int* in_sizes, int n_in,
                              void* d_out, int out_size) {
    const float* x = (const float*)d_in[0];
    const float* y = (const float*)d_in[1];
    const float* disp = (const float*)d_in[2];
    int B = in_sizes[0] / (C * H * W);
    int D = in_sizes[2] / (B * H * W);
    int smem = (C * YS + W * GS) * (int)sizeof(float);
    cudaFuncSetAttribute(cost_volume_kernel,
                         cudaFuncAttributeMaxDynamicSharedMemorySize, smem);
    cost_volume_kernel<<<B * H, NT, smem>>>(x, y, disp, (float*)d_out, D);
}

// round 3
// speedup vs baseline: 1.6333x; 1.1875x over previous
#include <cuda_runtime.h>

#define C 32
#define H 128
#define W 256
#define YS 36        // y_sh row stride ([jj][c] layout) = 144B; lane stride 144 % 128 = 16 -> conflict-free LDS.128
#define NJJ 321      // jj in [0, 320]
#define GO 66
#define GS 67
#define NT 512

typedef unsigned long long u64;

__device__ __forceinline__ u64 pack2(float lo, float hi) {
    u64 r; asm("mov.b64 %0, {%1, %2};" : "=l"(r) : "f"(lo), "f"(hi)); return r;
}
__device__ __forceinline__ void ffma2(u64& acc, u64 a, u64 b) {
    asm("fma.rn.f32x2 %0, %1, %2, %0;" : "+l"(acc) : "l"(a), "l"(b));
}
__device__ __forceinline__ u64 add2(u64 a, u64 b) {
    u64 r; asm("add.rn.f32x2 %0, %1, %2;" : "=l"(r) : "l"(a), "l"(b)); return r;
}
__device__ __forceinline__ float hadd2(u64 v) {
    float lo, hi; asm("mov.b64 {%0, %1}, %2;" : "=f"(lo), "=f"(hi) : "l"(v)); return lo + hi;
}

__global__ __launch_bounds__(NT, 2)
void cost_volume_kernel(const float* __restrict__ x, const float* __restrict__ y,
                        const float* __restrict__ disp, float* __restrict__ out,
                        int D) {
    extern __shared__ float sm[];
    float* y_sh = sm;                  // NJJ * YS, layout [jj][c], row jj holds y column (jj - 64)
    float* G_sh = sm + NJJ * YS;       // W * GS banded Gram

    const int bh = blockIdx.x;
    const int b = bh / H;
    const int h = bh - b * H;
    const int tid = threadIdx.x;
    const size_t HW = (size_t)H * W;
    const float* ybase = y + ((size_t)b * C * H + h) * W;
    const float* xbase = x + ((size_t)b * C * H + h) * W;

    // ---- Phase 1: stage y row transposed into smem, zero-padded borders
    // (the zero padding implements the reference's out-of-range mask).
    for (int i = tid; i < 64 * YS; i += NT) y_sh[i] = 0.0f;           // jj in [0,64)
    if (tid < YS) y_sh[320 * YS + tid] = 0.0f;                        // jj == 320
    {
        int c2 = tid >> 8;            // 0..1
        int j  = tid & 255;
        #pragma unroll
        for (int c0 = 0; c0 < C; c0 += 2) {
            int c = c0 + c2;
            y_sh[(j + 64) * YS + c] = ybase[(size_t)c * HW + j];
        }
    }

    // Warp layout: 16 w-columns per warp, lane halves split channels.
    const int lane = tid & 31;
    const int wp = tid >> 5;
    const int half = lane >> 4;        // 0: c in [0,16), 1: c in [16,32)
    const int wl = lane & 15;
    const int w = wp * 16 + wl;
    const int cbase = half * 16;
    const bool has_b = (w + 1 < W);

    // x columns w and w+1, packed as channel pairs for FFMA2.
    u64 xa[8], xb[8];
    #pragma unroll
    for (int k = 0; k < 8; k++) {
        float a0 = xbase[(size_t)(cbase + 2 * k) * HW + w];
        float a1 = xbase[(size_t)(cbase + 2 * k + 1) * HW + w];
        xa[k] = pack2(a0, a1);
        float b0 = has_b ? xbase[(size_t)(cbase + 2 * k) * HW + w + 1] : 0.f;
        float b1 = has_b ? xbase[(size_t)(cbase + 2 * k + 1) * HW + w + 1] : 0.f;
        xb[k] = pack2(b0, b1);
    }
    __syncthreads();

    // ---- Phase 2: banded Gram  G[w][o] = sum_c x[c][w] * y_sh[w+o][c]
    // Anti-diagonal pairing: (w, o0) and (w+1, o0-1) share y row jj = w+o0.
    #pragma unroll 2
    for (int o0 = 1; o0 <= 65; o0 += 2) {
        const ulonglong2* yp =
            (const ulonglong2*)(y_sh + (w + o0) * YS + cbase);
        ulonglong2 p0 = yp[0];
        ulonglong2 p1 = yp[1];
        ulonglong2 p2 = yp[2];
        ulonglong2 p3 = yp[3];
        u64 a0 = 0, a1 = 0, b0 = 0, b1 = 0;
        ffma2(a0, xa[0], p0.x);  ffma2(b0, xb[0], p0.x);
        ffma2(a1, xa[1], p0.y);  ffma2(b1, xb[1], p0.y);
        ffma2(a0, xa[2], p1.x);  ffma2(b0, xb[2], p1.x);
        ffma2(a1, xa[3], p1.y);  ffma2(b1, xb[3], p1.y);
        ffma2(a0, xa[4], p2.x);  ffma2(b0, xb[4], p2.x);
        ffma2(a1, xa[5], p2.y);  ffma2(b1, xb[5], p2.y);
        ffma2(a0, xa[6], p3.x);  ffma2(b0, xb[6], p3.x);
        ffma2(a1, xa[7], p3.y);  ffma2(b1, xb[7], p3.y);
        float av = hadd2(add2(a0, a1));
        float bv = hadd2(add2(b0, b1));
        av += __shfl_xor_sync(0xFFFFFFFFu, av, 16);
        bv += __shfl_xor_sync(0xFFFFFFFFu, bv, 16);
        // half 0 stores (w, o0); half 1 stores (w+1, o0-1) — disjoint banks.
        int addr = half ? ((w + 1) * GS + o0 - 1) : (w * GS + o0);
        float val = half ? bv : av;
        if (!half || has_b) G_sh[addr] = val;
    }
    // Cleanup: entries (w=0, even o), 33 of them.
    if (tid < 33) {
        int o = 2 * tid;
        float s = 0.f;
        #pragma unroll
        for (int c = 0; c < C; c++)
            s = fmaf(xbase[(size_t)c * HW], y_sh[o * YS + c], s);
        G_sh[o] = s;
    }
    __syncthreads();

    // ---- Phase 3: gather + lerp, float4-vectorized.
    const float* dbase = disp + ((size_t)b * D * H + h) * W;
    float* obase = out + ((size_t)b * D * H + h) * W;
    const int total4 = D * (W / 4);
    for (int i = tid; i < total4; i += NT) {
        int d = i >> 6;               // W/4 == 64
        int w4 = (i & 63) << 2;
        float4 dv = *(const float4*)(dbase + (size_t)d * HW + w4);
        float4 res;
        #pragma unroll
        for (int j = 0; j < 4; j++) {
            int ww = w4 + j;
            float dvj = (&dv.x)[j];
            float px = (float)ww - dvj;
            float x0f = floorf(px);
            float fx = px - x0f;
            int o = (int)x0f - ww + 64;
            float g0 = ((unsigned)o < GO) ? G_sh[ww * GS + o] : 0.f;
            float g1 = ((unsigned)(o + 1) < GO) ? G_sh[ww * GS + o + 1] : 0.f;
            (&res.x)[j] = (g0 + (g1 - g0) * fx) * (1.0f / C);
        }
        *(float4*)(obase + (size_t)d * HW + w4) = res;
    }
}

extern "C" void kernel_launch(void* const* d_in, const int* in_sizes, int n_in,
                              void* d_out, int out_size) {
    const float* x = (const float*)d_in[0];
    const float* y = (const float*)d_in[1];
    const float* disp = (const float*)d_in[2];
    int B = in_sizes[0] / (C * H * W);
    int D = in_sizes[2] / (B * H * W);
    int smem = (NJJ * YS + W * GS) * (int)sizeof(float);
    cudaFuncSetAttribute(cost_volume_kernel,
                         cudaFuncAttributeMaxDynamicSharedMemorySize, smem);
    cost_volume_kernel<<<B * H, NT, smem>>>(x, y, disp, (float*)d_out, D);
}

// round 4
// speedup vs baseline: 1.7738x; 1.0860x over previous
#include <cuda_runtime.h>

#define C 32
#define H 128
#define W 256
#define YS 36        // y_sh row stride ([jj][c] layout), 144B: lane bank stride 4 -> conflict-free
#define NJJ 321      // jj in [0, 320]
#define GO 66
#define GS 67
#define GROWS 257    // pad one row so the b-store for w=255 -> row 256 is unconditional
#define NT 256

typedef unsigned long long u64;

__device__ __forceinline__ u64 pack2(float lo, float hi) {
    u64 r; asm("mov.b64 %0, {%1, %2};" : "=l"(r) : "f"(lo), "f"(hi)); return r;
}
__device__ __forceinline__ void ffma2(u64& acc, u64 a, u64 b) {
    asm("fma.rn.f32x2 %0, %1, %2, %0;" : "+l"(acc) : "l"(a), "l"(b));
}
__device__ __forceinline__ u64 add2(u64 a, u64 b) {
    u64 r; asm("add.rn.f32x2 %0, %1, %2;" : "=l"(r) : "l"(a), "l"(b)); return r;
}
__device__ __forceinline__ float hadd2(u64 v) {
    float lo, hi; asm("mov.b64 {%0, %1}, %2;" : "=f"(lo), "=f"(hi) : "l"(v)); return lo + hi;
}

__global__ __launch_bounds__(NT, 2)
void cost_volume_kernel(const float* __restrict__ x, const float* __restrict__ y,
                        const float* __restrict__ disp, float* __restrict__ out,
                        int D) {
    extern __shared__ float sm[];
    float* y_sh = sm;                  // NJJ * YS   ([jj][c]; row jj = y column (jj-64))
    float* G_sh = sm + NJJ * YS;       // GROWS * GS banded Gram

    const int bh = blockIdx.x;
    const int b = bh / H;
    const int h = bh - b * H;
    const int tid = threadIdx.x;
    const size_t HW = (size_t)H * W;
    const float* ybase = y + ((size_t)b * C * H + h) * W;
    const float* xbase = x + ((size_t)b * C * H + h) * W;

    // ---- Phase 1: zero-pad borders (implements the reference's zero-padding
    // mask), then stage y row transposed into smem, STS.128-vectorized.
    for (int i = tid; i < 64 * YS; i += NT) y_sh[i] = 0.0f;   // jj in [0,64)
    if (tid < YS) y_sh[320 * YS + tid] = 0.0f;                // jj == 320
    {
        const float* src = ybase + tid;          // column j = tid
        float* dst = y_sh + (tid + 64) * YS;
        #pragma unroll
        for (int c = 0; c < C; c += 4) {
            float v0 = src[(size_t)(c + 0) * HW];
            float v1 = src[(size_t)(c + 1) * HW];
            float v2 = src[(size_t)(c + 2) * HW];
            float v3 = src[(size_t)(c + 3) * HW];
            *(float4*)(dst + c) = make_float4(v0, v1, v2, v3);
        }
    }

    // x columns w and w+1, all 32 channels, packed for FFMA2.
    const int w = tid;                // blockDim.x == W
    const bool has_b = (w + 1 < W);
    u64 xa[16], xb[16];
    #pragma unroll
    for (int k = 0; k < 16; k++) {
        float a0 = xbase[(size_t)(2 * k) * HW + w];
        float a1 = xbase[(size_t)(2 * k + 1) * HW + w];
        xa[k] = pack2(a0, a1);
        float b0 = has_b ? xbase[(size_t)(2 * k) * HW + w + 1] : 0.f;
        float b1 = has_b ? xbase[(size_t)(2 * k + 1) * HW + w + 1] : 0.f;
        xb[k] = pack2(b0, b1);
    }
    __syncthreads();

    // ---- Phase 2: banded Gram  G[w][o] = sum_c x[c][w] * y_sh[w+o][c]
    // Anti-diagonal pairing: (w, o0) and (w+1, o0-1) share row jj = w + o0.
    const float* yrow = y_sh + w * YS;
    float* ga = G_sh + w * GS;
    float* gb = G_sh + (w + 1) * GS;
    #pragma unroll 1
    for (int o0 = 1; o0 <= 65; o0 += 2) {
        const ulonglong2* yp = (const ulonglong2*)(yrow + o0 * YS);
        ulonglong2 q0 = yp[0], q1 = yp[1], q2 = yp[2], q3 = yp[3];
        ulonglong2 q4 = yp[4], q5 = yp[5], q6 = yp[6], q7 = yp[7];
        u64 a0 = 0, a1 = 0, a2 = 0, a3 = 0;
        u64 b0 = 0, b1 = 0, b2 = 0, b3 = 0;
        ffma2(a0, xa[0],  q0.x);  ffma2(b0, xb[0],  q0.x);
        ffma2(a1, xa[1],  q0.y);  ffma2(b1, xb[1],  q0.y);
        ffma2(a2, xa[2],  q1.x);  ffma2(b2, xb[2],  q1.x);
        ffma2(a3, xa[3],  q1.y);  ffma2(b3, xb[3],  q1.y);
        ffma2(a0, xa[4],  q2.x);  ffma2(b0, xb[4],  q2.x);
        ffma2(a1, xa[5],  q2.y);  ffma2(b1, xb[5],  q2.y);
        ffma2(a2, xa[6],  q3.x);  ffma2(b2, xb[6],  q3.x);
        ffma2(a3, xa[7],  q3.y);  ffma2(b3, xb[7],  q3.y);
        ffma2(a0, xa[8],  q4.x);  ffma2(b0, xb[8],  q4.x);
        ffma2(a1, xa[9],  q4.y);  ffma2(b1, xb[9],  q4.y);
        ffma2(a2, xa[10], q5.x);  ffma2(b2, xb[10], q5.x);
        ffma2(a3, xa[11], q5.y);  ffma2(b3, xb[11], q5.y);
        ffma2(a0, xa[12], q6.x);  ffma2(b0, xb[12], q6.x);
        ffma2(a1, xa[13], q6.y);  ffma2(b1, xb[13], q6.y);
        ffma2(a2, xa[14], q7.x);  ffma2(b2, xb[14], q7.x);
        ffma2(a3, xa[15], q7.y);  ffma2(b3, xb[15], q7.y);
        ga[o0]     = hadd2(add2(add2(a0, a1), add2(a2, a3)));
        gb[o0 - 1] = hadd2(add2(add2(b0, b1), add2(b2, b3)));
    }
    // Cleanup: entries (w=0, even o), 33 of them.
    if (tid < 33) {
        int o = 2 * tid;
        float s = 0.f;
        #pragma unroll
        for (int c = 0; c < C; c++)
            s = fmaf(xbase[(size_t)c * HW], y_sh[o * YS + c], s);
        G_sh[o] = s;
    }

    // ---- Phase 3 prologue: issue all disp loads BEFORE the barrier so their
    // gmem latency hides under other warps' phase-2 tail.
    const float* dbase = disp + ((size_t)b * D * H + h) * W;
    float* obase = out + ((size_t)b * D * H + h) * W;

    if (D == 48) {
        float4 dv[12];
        #pragma unroll
        for (int k = 0; k < 12; k++) {
            int i = tid + k * NT;
            int d = i >> 6;               // W/4 == 64
            int w4 = (i & 63) << 2;
            dv[k] = *(const float4*)(dbase + (size_t)d * HW + w4);
        }
        __syncthreads();
        #pragma unroll
        for (int k = 0; k < 12; k++) {
            int i = tid + k * NT;
            int d = i >> 6;
            int w4 = (i & 63) << 2;
            float4 res;
            #pragma unroll
            for (int j = 0; j < 4; j++) {
                int ww = w4 + j;
                float dvj = (&dv[k].x)[j];
                float px = (float)ww - dvj;
                float x0f = floorf(px);
                float fx = px - x0f;
                int o = (int)x0f - ww + 64;
                float g0 = ((unsigned)o < GO) ? G_sh[ww * GS + o] : 0.f;
                float g1 = ((unsigned)(o + 1) < GO) ? G_sh[ww * GS + o + 1] : 0.f;
                (&res.x)[j] = (g0 + (g1 - g0) * fx) * (1.0f / C);
            }
            *(float4*)(obase + (size_t)d * HW + w4) = res;
        }
    } else {
        __syncthreads();
        const int total4 = D * (W / 4);
        #pragma unroll 4
        for (int i = tid; i < total4; i += NT) {
            int d = i >> 6;
            int w4 = (i & 63) << 2;
            float4 dv = *(const float4*)(dbase + (size_t)d * HW + w4);
            float4 res;
            #pragma unroll
            for (int j = 0; j < 4; j++) {
                int ww = w4 + j;
                float dvj = (&dv.x)[j];
                float px = (float)ww - dvj;
                float x0f = floorf(px);
                float fx = px - x0f;
                int o = (int)x0f - ww + 64;
                float g0 = ((unsigned)o < GO) ? G_sh[ww * GS + o] : 0.f;
                float g1 = ((unsigned)(o + 1) < GO) ? G_sh[ww * GS + o + 1] : 0.f;
                (&res.x)[j] = (g0 + (g1 - g0) * fx) * (1.0f / C);
            }
            *(float4*)(obase + (size_t)d * HW + w4) = res;
        }
    }
}

extern "C" void kernel_launch(void* const* d_in, const int* in_sizes, int n_in,
                              void* d_out, int out_size) {
    const float* x = (const float*)d_in[0];
    const float* y = (const float*)d_in[1];
    const float* disp = (const float*)d_in[2];
    int B = in_sizes[0] / (C * H * W);
    int D = in_sizes[2] / (B * H * W);
    int smem = (NJJ * YS + GROWS * GS) * (int)sizeof(float);
    cudaFuncSetAttribute(cost_volume_kernel,
                         cudaFuncAttributeMaxDynamicSharedMemorySize, smem);
    cost_volume_kernel<<<B * H, NT, smem>>>(x, y, disp, (float*)d_out, D);
}